// round 10
// baseline (speedup 1.0000x reference)
#include <cuda_runtime.h>
#include <math_constants.h>

#define BB   512
#define NN   1000
#define DD   128
#define HH   8
#define HIDD 128
#define CHUNK 64
#define NCHUNK ((NN + CHUNK - 1) / CHUNK)   // 16

// Scratch (static __device__ — no allocation allowed)
__device__ float g_A[BB * HH * DD];   // [b][c*8+h], 0.25*fold(q,Wk_mha)
__device__ float g_m[BB * HH * DD];   // [b][h*128+c], softmax-normalized
__device__ float g_y[BB * HIDD];      // [b][c], pointer query vector (norm folded)

// ---------------------------------------------------------------------------
// K0: q = state @ Wq  (per b), then A[b][c][h] = 0.25*sum_d Wk_mha[c][h*16+d]*q[h*16+d]
// grid = B/4 blocks, 256 threads, 4 b's per block.
// ---------------------------------------------------------------------------
__global__ void __launch_bounds__(256)
k0_qa(const float* __restrict__ state,
      const float* __restrict__ Wq,
      const float* __restrict__ Wk_mha) {
    __shared__ float st_s[4][384];
    __shared__ float q_s[4][HIDD];
    int t = threadIdx.x;
    int b0 = blockIdx.x * 4;

    for (int i = t; i < 4 * 384; i += 256) {
        int bl = i / 384, c = i % 384;
        st_s[bl][c] = state[(b0 + bl) * 384 + c];
    }
    __syncthreads();

    // q: 4*128 outputs, 2 per thread
    #pragma unroll
    for (int r = 0; r < 2; ++r) {
        int idx = r * 256 + t;
        int bl = idx >> 7, u = idx & 127;
        float acc = 0.f;
        #pragma unroll 4
        for (int i = 0; i < 384; ++i)
            acc += st_s[bl][i] * Wq[i * HIDD + u];
        q_s[bl][u] = acc;
    }
    __syncthreads();

    // A: 4*8*128 outputs, 16 per thread (16 MACs each)
    #pragma unroll
    for (int r = 0; r < 16; ++r) {
        int idx = r * 256 + t;
        int bl = idx >> 10, rem = idx & 1023;
        int h = rem >> 7, c = rem & 127;
        const float* wrow = Wk_mha + c * HIDD + h * 16;
        const float* qp   = &q_s[bl][h * 16];
        float acc = 0.f;
        #pragma unroll
        for (int d = 0; d < 16; ++d) acc += wrow[d] * qp[d];
        g_A[(b0 + bl) * (HH * DD) + c * 8 + h] = acc * 0.25f;   // norm_h folded
    }
}

// ---------------------------------------------------------------------------
// K1: per-b fused MHA: comp -> online masked softmax -> m[h][c] (normalized).
// One CTA per b, 256 threads. Single pass over context (flash-style).
// ---------------------------------------------------------------------------
__global__ void __launch_bounds__(256)
k1_mha(const float* __restrict__ ctx, const int* __restrict__ mask) {
    __shared__ float ctx_s[CHUNK * 132];   // swizzled chunk
    __shared__ float At_s[DD * HH];        // [c][h]
    __shared__ float cb_s[HH][72];         // chunk logits -> chunk p
    __shared__ float f_s[HH];
    __shared__ float d_s[HH];

    int t    = threadIdx.x;
    int b    = blockIdx.x;
    int lane = t & 31, w = t >> 5;     // warp w == head w in phase 3
    int jj   = t >> 2, q = t & 3;      // phase 2 roles
    int g    = t >> 7, c = t & 127;    // phase 4 roles

    #pragma unroll
    for (int r = 0; r < 4; ++r)
        At_s[r * 256 + t] = g_A[b * 1024 + r * 256 + t];

    float mAcc[4] = {0.f, 0.f, 0.f, 0.f};
    float runM = -CUDART_INF_F, runD = 0.f;

    const float* cbase = ctx + (size_t)b * NN * DD;
    const int*   mb    = mask + b * NN;
    const int cblk = c >> 5, crem = c & 31;

    for (int ch = 0; ch < NCHUNK; ++ch) {
        int j0 = ch * CHUNK;
        int len = min(CHUNK, NN - j0);
        __syncthreads();   // previous phase-4 readers done with ctx_s / cb_s

        // stage chunk (coalesced float4 reads, swizzled scalar stores)
        const float4* src = (const float4*)(cbase + (size_t)j0 * DD);
        int n4 = len * 32;
        for (int i = t; i < n4; i += 256) {
            float4 v = src[i];
            int j = i >> 5, cc = (i & 31) * 4;
            int off = j * 132 + (cc >> 5) * 33 + (cc & 31);
            ctx_s[off] = v.x; ctx_s[off + 1] = v.y;
            ctx_s[off + 2] = v.z; ctx_s[off + 3] = v.w;
        }
        __syncthreads();

        // phase 2: logits. thread (jj,q) covers row jj, 32-col slice q.
        float acc[8];
        #pragma unroll
        for (int h = 0; h < 8; ++h) acc[h] = 0.f;
        {
            const float4* At4 = (const float4*)At_s;
            int rowoff = jj * 132 + q * 33;
            int cbas   = q * 32;
            #pragma unroll
            for (int cc = 0; cc < 32; ++cc) {
                float xv = ctx_s[rowoff + cc];
                float4 a0 = At4[(cbas + cc) * 2];
                float4 a1 = At4[(cbas + cc) * 2 + 1];
                acc[0] += xv * a0.x; acc[1] += xv * a0.y;
                acc[2] += xv * a0.z; acc[3] += xv * a0.w;
                acc[4] += xv * a1.x; acc[5] += xv * a1.y;
                acc[6] += xv * a1.z; acc[7] += xv * a1.w;
            }
        }
        #pragma unroll
        for (int h = 0; h < 8; ++h) {
            acc[h] += __shfl_xor_sync(0xffffffffu, acc[h], 1);
            acc[h] += __shfl_xor_sync(0xffffffffu, acc[h], 2);
        }
        if (q == 0) {
            bool ok = (jj < len) && (mb[j0 + jj] == 0);
            #pragma unroll
            for (int h = 0; h < 8; ++h)
                cb_s[h][jj] = ok ? acc[h] : -CUDART_INF_F;
        }
        __syncthreads();

        // phase 3: warp w = head w online softmax update
        float v0 = cb_s[w][lane], v1 = cb_s[w][lane + 32];
        float cm = fmaxf(v0, v1);
        #pragma unroll
        for (int o = 16; o > 0; o >>= 1)
            cm = fmaxf(cm, __shfl_xor_sync(0xffffffffu, cm, o));
        float newM = fmaxf(runM, cm);
        float f  = __expf(runM - newM);
        float p0 = __expf(v0 - newM);
        float p1 = __expf(v1 - newM);
        cb_s[w][lane] = p0; cb_s[w][lane + 32] = p1;
        float s = p0 + p1;
        #pragma unroll
        for (int o = 16; o > 0; o >>= 1)
            s += __shfl_xor_sync(0xffffffffu, s, o);
        runD = runD * f + s;
        runM = newM;
        if (lane == 0) f_s[w] = f;
        __syncthreads();

        // phase 4: m[h][c] accumulation (rescale + rank-CHUNK update)
        {
            float ff0 = f_s[g * 4 + 0], ff1 = f_s[g * 4 + 1];
            float ff2 = f_s[g * 4 + 2], ff3 = f_s[g * 4 + 3];
            mAcc[0] *= ff0; mAcc[1] *= ff1; mAcc[2] *= ff2; mAcc[3] *= ff3;
            int coff = cblk * 33 + crem;
            #pragma unroll 8
            for (int j = 0; j < CHUNK; ++j) {
                float xv = ctx_s[j * 132 + coff];
                mAcc[0] += cb_s[g * 4 + 0][j] * xv;
                mAcc[1] += cb_s[g * 4 + 1][j] * xv;
                mAcc[2] += cb_s[g * 4 + 2][j] * xv;
                mAcc[3] += cb_s[g * 4 + 3][j] * xv;
            }
        }
    }
    __syncthreads();
    if (lane == 0) d_s[w] = runD;
    __syncthreads();
    #pragma unroll
    for (int hh = 0; hh < 4; ++hh) {
        int h = g * 4 + hh;
        g_m[b * 1024 + h * 128 + c] = mAcc[hh] / d_s[h];
    }
}

// ---------------------------------------------------------------------------
// K2: y[b] = norm_p * Wk @ (Wfc applied to x_pre) ... small matvec chain per b.
// grid = B/8 blocks, 8 b's per block, weights streamed from L2.
// ---------------------------------------------------------------------------
__global__ void __launch_bounds__(256)
k2_y(const float* __restrict__ Wv,
     const float* __restrict__ Wfc,
     const float* __restrict__ Wk) {
    __shared__ float m_s[8][1024];
    __shared__ float xp_s[8][128];
    __shared__ float x_s[8][128];
    int t = threadIdx.x;
    int b0 = blockIdx.x * 8;

    for (int i = t; i < 8 * 1024; i += 256)
        ((float*)m_s)[i] = g_m[b0 * 1024 + i];
    __syncthreads();

    // x_pre[u] = sum_c m[h(u)][c] * Wv[c][u]
    #pragma unroll
    for (int r = 0; r < 4; ++r) {
        int idx = r * 256 + t;
        int bl = idx >> 7, u = idx & 127, h = u >> 4;
        float acc = 0.f;
        #pragma unroll 4
        for (int cc = 0; cc < 128; ++cc)
            acc += m_s[bl][h * 128 + cc] * Wv[cc * 128 + u];
        xp_s[bl][u] = acc;
    }
    __syncthreads();

    // x = x_pre @ Wfc
    #pragma unroll
    for (int r = 0; r < 4; ++r) {
        int idx = r * 256 + t;
        int bl = idx >> 7, u = idx & 127;
        float acc = 0.f;
        #pragma unroll 4
        for (int k = 0; k < 128; ++k)
            acc += xp_s[bl][k] * Wfc[k * 128 + u];
        x_s[bl][u] = acc;
    }
    __syncthreads();

    // y[c] = norm_p * sum_t Wk[c][t] * x[t]
    const float normp = 0.08838834764831845f;   // 1/sqrt(128)
    #pragma unroll
    for (int r = 0; r < 4; ++r) {
        int idx = r * 256 + t;
        int bl = idx >> 7, cc = idx & 127;
        float acc = 0.f;
        #pragma unroll 4
        for (int k = 0; k < 128; ++k)
            acc += Wk[cc * 128 + k] * x_s[bl][k];
        g_y[(b0 + bl) * 128 + cc] = acc * normp;
    }
}

// ---------------------------------------------------------------------------
// K3: pointer head. compat = ctx . y, tanh*5, mask, max-sub, softmax(/T).
// One CTA per b, second (and last) pass over context.
// ---------------------------------------------------------------------------
__global__ void __launch_bounds__(256)
k3_ptr(const float* __restrict__ ctx, const int* __restrict__ mask,
       const void* __restrict__ Tin, float* __restrict__ out) {
    __shared__ float ctx_s[CHUNK * 132];
    __shared__ float u_s[NN];
    __shared__ float red_s[8];
    __shared__ float bm_s, bs_s;
    int t = threadIdx.x;
    int b = blockIdx.x;
    int lane = t & 31, w = t >> 5;
    int jj = t >> 2, q = t & 3;

    float yr[32];
    {
        const float* yb = g_y + b * 128 + q * 32;
        #pragma unroll
        for (int i = 0; i < 32; ++i) yr[i] = yb[i];
    }

    const float* cbase = ctx + (size_t)b * NN * DD;
    const int*   mb    = mask + b * NN;

    for (int ch = 0; ch < NCHUNK; ++ch) {
        int j0 = ch * CHUNK;
        int len = min(CHUNK, NN - j0);
        __syncthreads();
        const float4* src = (const float4*)(cbase + (size_t)j0 * DD);
        int n4 = len * 32;
        for (int i = t; i < n4; i += 256) {
            float4 v = src[i];
            int j = i >> 5, cc = (i & 31) * 4;
            int off = j * 132 + (cc >> 5) * 33 + (cc & 31);
            ctx_s[off] = v.x; ctx_s[off + 1] = v.y;
            ctx_s[off + 2] = v.z; ctx_s[off + 3] = v.w;
        }
        __syncthreads();

        float acc = 0.f;
        int rowoff = jj * 132 + q * 33;
        #pragma unroll
        for (int cc = 0; cc < 32; ++cc)
            acc += ctx_s[rowoff + cc] * yr[cc];
        acc += __shfl_xor_sync(0xffffffffu, acc, 1);
        acc += __shfl_xor_sync(0xffffffffu, acc, 2);
        if (q == 0 && jj < len) {
            bool msk = (mb[j0 + jj] != 0);
            u_s[j0 + jj] = msk ? -CUDART_INF_F : tanhf(acc) * 5.f;
        }
    }
    __syncthreads();

    // T may arrive as int32/int64 or float32 — detect robustly.
    float Tval;
    {
        float tf = *(const float*)Tin;
        int   ti = *(const int*)Tin;
        Tval = (tf > 1e-6f && tf < 1e6f) ? tf : (float)ti;
    }
    float invT = 1.f / Tval;

    // block max
    float mx = -CUDART_INF_F;
    for (int j = t; j < NN; j += 256) mx = fmaxf(mx, u_s[j]);
    #pragma unroll
    for (int o = 16; o > 0; o >>= 1)
        mx = fmaxf(mx, __shfl_xor_sync(0xffffffffu, mx, o));
    if (lane == 0) red_s[w] = mx;
    __syncthreads();
    if (w == 0) {
        float v = red_s[lane & 7];
        #pragma unroll
        for (int o = 4; o > 0; o >>= 1)
            v = fmaxf(v, __shfl_xor_sync(0xffffffffu, v, o));
        if (lane == 0) bm_s = v;
    }
    __syncthreads();
    mx = bm_s;

    // exp + block sum
    float s = 0.f;
    for (int j = t; j < NN; j += 256) {
        float p = __expf((u_s[j] - mx) * invT);
        u_s[j] = p;
        s += p;
    }
    #pragma unroll
    for (int o = 16; o > 0; o >>= 1)
        s += __shfl_xor_sync(0xffffffffu, s, o);
    if (lane == 0) red_s[w] = s;
    __syncthreads();
    if (w == 0) {
        float v = red_s[lane & 7];
        #pragma unroll
        for (int o = 4; o > 0; o >>= 1)
            v += __shfl_xor_sync(0xffffffffu, v, o);
        if (lane == 0) bs_s = v;
    }
    __syncthreads();
    float inv = 1.f / bs_s;
    for (int j = t; j < NN; j += 256)
        out[(size_t)b * NN + j] = u_s[j] * inv;
}

// ---------------------------------------------------------------------------
extern "C" void kernel_launch(void* const* d_in, const int* in_sizes, int n_in,
                              void* d_out, int out_size) {
    const float* state  = (const float*)d_in[0];
    const float* ctx    = (const float*)d_in[1];
    const int*   mask   = (const int*)d_in[2];
    const float* Wq     = (const float*)d_in[3];
    const float* Wk_mha = (const float*)d_in[4];
    const float* Wv     = (const float*)d_in[5];
    const float* Wfc    = (const float*)d_in[6];
    const float* Wk     = (const float*)d_in[7];
    const void*  Tin    = d_in[8];
    float* out = (float*)d_out;

    k0_qa<<<BB / 4, 256>>>(state, Wq, Wk_mha);
    k1_mha<<<BB, 256>>>(ctx, mask);
    k2_y<<<BB / 8, 256>>>(Wv, Wfc, Wk);
    k3_ptr<<<BB, 256>>>(ctx, mask, Tin, out);
}

// round 15
// speedup vs baseline: 1.3881x; 1.3881x over previous
#include <cuda_runtime.h>
#include <math_constants.h>

#define BB   512
#define NN   1000
#define DD   128
#define HH   8
#define HIDD 128
#define CHUNK 64
#define NCHUNK ((NN + CHUNK - 1) / CHUNK)   // 16

__device__ float g_A[BB * HH * DD];   // [b][c*8+h], 0.25*fold(q,Wk_mha)
__device__ float g_m[BB * HH * DD];   // [b][h*128+c], softmax-normalized
__device__ float g_y[BB * HIDD];      // [b][c]

// ---------------------------------------------------------------------------
// K0: q = state @ Wq, then A[b][c][h] = 0.25*sum_d Wk_mha[c][h*16+d]*q[h*16+d]
// A-phase is warp-cooperative: 16 lanes per output, coalesced 64B reads + shfl.
// ---------------------------------------------------------------------------
__global__ void __launch_bounds__(256)
k0_qa(const float* __restrict__ state,
      const float* __restrict__ Wq,
      const float* __restrict__ Wk_mha) {
    __shared__ float st_s[4][384];
    __shared__ float q_s[4][HIDD];
    int t = threadIdx.x;
    int lane = t & 31, w = t >> 5;
    int b0 = blockIdx.x * 4;

    for (int i = t; i < 4 * 384; i += 256) {
        int bl = i / 384, c = i % 384;
        st_s[bl][c] = state[(b0 + bl) * 384 + c];
    }
    __syncthreads();

    #pragma unroll
    for (int r = 0; r < 2; ++r) {
        int idx = r * 256 + t;
        int bl = idx >> 7, u = idx & 127;
        float acc = 0.f;
        #pragma unroll 4
        for (int i = 0; i < 384; ++i)
            acc += st_s[bl][i] * Wq[i * HIDD + u];
        q_s[bl][u] = acc;
    }
    __syncthreads();

    // A-phase: each warp produces 2 outputs per iter; 16 lanes read 16
    // consecutive floats (coalesced) and shfl-reduce.
    int lane16 = lane & 15, half = lane >> 4;
    for (int it = w; it < 2048; it += 8) {
        int outIdx = it * 2 + half;            // 0..4095 = (bl,h,c)
        int bl = outIdx >> 10, rem = outIdx & 1023;
        int h = rem >> 7, cc = rem & 127;
        float v = Wk_mha[cc * HIDD + h * 16 + lane16] * q_s[bl][h * 16 + lane16];
        v += __shfl_xor_sync(0xffffffffu, v, 8);
        v += __shfl_xor_sync(0xffffffffu, v, 4);
        v += __shfl_xor_sync(0xffffffffu, v, 2);
        v += __shfl_xor_sync(0xffffffffu, v, 1);
        if (lane16 == 0)
            g_A[(b0 + bl) * 1024 + cc * 8 + h] = v * 0.25f;
    }
}

// ---------------------------------------------------------------------------
// K1: fused single-query MHA. At_s uses padded q-block layout (bank-conflict
// free); chunk probabilities stored transposed cbT[j][h] for float4 reads.
// ---------------------------------------------------------------------------
__global__ void __launch_bounds__(256)
k1_mha(const float* __restrict__ ctx, const int* __restrict__ mask) {
    __shared__ float ctx_s[CHUNK * 132];   // swizzled chunk
    __shared__ float At_s[4 * 264];        // q-block padded: off = (c>>5)*264+(c&31)*8+h
    __shared__ float cbT[CHUNK][8];        // [j][h] logits -> p
    __shared__ float f_s[HH];
    __shared__ float d_s[HH];

    int t    = threadIdx.x;
    int b    = blockIdx.x;
    int lane = t & 31, w = t >> 5;     // phase 3: warp w == head w
    int jj   = t >> 2, q = t & 3;      // phase 2 roles
    int g    = t >> 7, c = t & 127;    // phase 4 roles

    #pragma unroll
    for (int r = 0; r < 4; ++r) {
        int idx = r * 256 + t;          // = c*8+h
        int cc_ = idx >> 3, h_ = idx & 7;
        At_s[(cc_ >> 5) * 264 + (cc_ & 31) * 8 + h_] = g_A[b * 1024 + idx];
    }

    float mAcc[4] = {0.f, 0.f, 0.f, 0.f};
    float runM = -CUDART_INF_F, runD = 0.f;

    const float* cbase = ctx + (size_t)b * NN * DD;
    const int*   mb    = mask + b * NN;
    const int cblk = c >> 5, crem = c & 31;

    for (int ch = 0; ch < NCHUNK; ++ch) {
        int j0 = ch * CHUNK;
        int len = min(CHUNK, NN - j0);
        __syncthreads();

        // stage chunk (coalesced float4 reads, swizzled scalar stores)
        const float4* src = (const float4*)(cbase + (size_t)j0 * DD);
        int n4 = len * 32;
        for (int i = t; i < n4; i += 256) {
            float4 v = src[i];
            int j = i >> 5, cc = (i & 31) * 4;
            int off = j * 132 + (cc >> 5) * 33 + (cc & 31);
            ctx_s[off] = v.x; ctx_s[off + 1] = v.y;
            ctx_s[off + 2] = v.z; ctx_s[off + 3] = v.w;
        }
        __syncthreads();

        // phase 2: logits. thread (jj,q): row jj, 32-col slice q.
        float acc[8];
        #pragma unroll
        for (int h = 0; h < 8; ++h) acc[h] = 0.f;
        {
            const float4* At4 = (const float4*)At_s;
            int qbase  = q * 66;                 // float4 index of q-block
            int rowoff = jj * 132 + q * 33;
            #pragma unroll
            for (int cc = 0; cc < 32; ++cc) {
                float xv = ctx_s[rowoff + cc];
                float4 a0 = At4[qbase + cc * 2];
                float4 a1 = At4[qbase + cc * 2 + 1];
                acc[0] += xv * a0.x; acc[1] += xv * a0.y;
                acc[2] += xv * a0.z; acc[3] += xv * a0.w;
                acc[4] += xv * a1.x; acc[5] += xv * a1.y;
                acc[6] += xv * a1.z; acc[7] += xv * a1.w;
            }
        }
        #pragma unroll
        for (int h = 0; h < 8; ++h) {
            acc[h] += __shfl_xor_sync(0xffffffffu, acc[h], 1);
            acc[h] += __shfl_xor_sync(0xffffffffu, acc[h], 2);
        }
        if (q == 0) {
            bool ok = (jj < len) && (mb[j0 + jj] == 0);
            float4 lo, hi;
            lo.x = ok ? acc[0] : -CUDART_INF_F;
            lo.y = ok ? acc[1] : -CUDART_INF_F;
            lo.z = ok ? acc[2] : -CUDART_INF_F;
            lo.w = ok ? acc[3] : -CUDART_INF_F;
            hi.x = ok ? acc[4] : -CUDART_INF_F;
            hi.y = ok ? acc[5] : -CUDART_INF_F;
            hi.z = ok ? acc[6] : -CUDART_INF_F;
            hi.w = ok ? acc[7] : -CUDART_INF_F;
            *(float4*)&cbT[jj][0] = lo;
            *(float4*)&cbT[jj][4] = hi;
        }
        __syncthreads();

        // phase 3: warp w = head w online softmax update
        float v0 = cbT[lane][w], v1 = cbT[lane + 32][w];
        float cm = fmaxf(v0, v1);
        #pragma unroll
        for (int o = 16; o > 0; o >>= 1)
            cm = fmaxf(cm, __shfl_xor_sync(0xffffffffu, cm, o));
        float newM = fmaxf(runM, cm);
        float f  = __expf(runM - newM);
        float p0 = __expf(v0 - newM);
        float p1 = __expf(v1 - newM);
        cbT[lane][w] = p0; cbT[lane + 32][w] = p1;
        float s = p0 + p1;
        #pragma unroll
        for (int o = 16; o > 0; o >>= 1)
            s += __shfl_xor_sync(0xffffffffu, s, o);
        runD = runD * f + s;
        runM = newM;
        if (lane == 0) f_s[w] = f;
        __syncthreads();

        // phase 4: m[h][c] accumulation; one float4 p-load per j.
        {
            float ff0 = f_s[g * 4 + 0], ff1 = f_s[g * 4 + 1];
            float ff2 = f_s[g * 4 + 2], ff3 = f_s[g * 4 + 3];
            mAcc[0] *= ff0; mAcc[1] *= ff1; mAcc[2] *= ff2; mAcc[3] *= ff3;
            int coff = cblk * 33 + crem;
            #pragma unroll 8
            for (int j = 0; j < CHUNK; ++j) {
                float xv = ctx_s[j * 132 + coff];
                float4 p = *(const float4*)&cbT[j][g * 4];
                mAcc[0] += p.x * xv;
                mAcc[1] += p.y * xv;
                mAcc[2] += p.z * xv;
                mAcc[3] += p.w * xv;
            }
        }
    }
    __syncthreads();
    if (lane == 0) d_s[w] = runD;
    __syncthreads();
    #pragma unroll
    for (int hh = 0; hh < 4; ++hh) {
        int h = g * 4 + hh;
        g_m[b * 1024 + h * 128 + c] = mAcc[hh] / d_s[h];
    }
}

// ---------------------------------------------------------------------------
// K2: y[b] = norm_p * Wk @ (Wfc @ (Wv-contraction of m)). 8 b's per block.
// ---------------------------------------------------------------------------
__global__ void __launch_bounds__(256)
k2_y(const float* __restrict__ Wv,
     const float* __restrict__ Wfc,
     const float* __restrict__ Wk) {
    __shared__ float m_s[8][1024];
    __shared__ float xp_s[8][128];
    __shared__ float x_s[8][128];
    int t = threadIdx.x;
    int b0 = blockIdx.x * 8;

    for (int i = t; i < 8 * 1024; i += 256)
        ((float*)m_s)[i] = g_m[b0 * 1024 + i];
    __syncthreads();

    #pragma unroll
    for (int r = 0; r < 4; ++r) {
        int idx = r * 256 + t;
        int bl = idx >> 7, u = idx & 127, h = u >> 4;
        float acc = 0.f;
        #pragma unroll 4
        for (int cc = 0; cc < 128; ++cc)
            acc += m_s[bl][h * 128 + cc] * Wv[cc * 128 + u];
        xp_s[bl][u] = acc;
    }
    __syncthreads();

    #pragma unroll
    for (int r = 0; r < 4; ++r) {
        int idx = r * 256 + t;
        int bl = idx >> 7, u = idx & 127;
        float acc = 0.f;
        #pragma unroll 4
        for (int k = 0; k < 128; ++k)
            acc += xp_s[bl][k] * Wfc[k * 128 + u];
        x_s[bl][u] = acc;
    }
    __syncthreads();

    const float normp = 0.08838834764831845f;   // 1/sqrt(128)
    #pragma unroll
    for (int r = 0; r < 4; ++r) {
        int idx = r * 256 + t;
        int bl = idx >> 7, cc = idx & 127;
        float acc = 0.f;
        #pragma unroll 4
        for (int k = 0; k < 128; ++k)
            acc += Wk[cc * 128 + k] * x_s[bl][k];
        g_y[(b0 + bl) * 128 + cc] = acc * normp;
    }
}

// ---------------------------------------------------------------------------
// K3: pointer head (unchanged — 58 µs, near DRAM roofline).
// ---------------------------------------------------------------------------
__global__ void __launch_bounds__(256)
k3_ptr(const float* __restrict__ ctx, const int* __restrict__ mask,
       const void* __restrict__ Tin, float* __restrict__ out) {
    __shared__ float ctx_s[CHUNK * 132];
    __shared__ float u_s[NN];
    __shared__ float red_s[8];
    __shared__ float bm_s, bs_s;
    int t = threadIdx.x;
    int b = blockIdx.x;
    int lane = t & 31, w = t >> 5;
    int jj = t >> 2, q = t & 3;

    float yr[32];
    {
        const float* yb = g_y + b * 128 + q * 32;
        #pragma unroll
        for (int i = 0; i < 32; ++i) yr[i] = yb[i];
    }

    const float* cbase = ctx + (size_t)b * NN * DD;
    const int*   mb    = mask + b * NN;

    for (int ch = 0; ch < NCHUNK; ++ch) {
        int j0 = ch * CHUNK;
        int len = min(CHUNK, NN - j0);
        __syncthreads();
        const float4* src = (const float4*)(cbase + (size_t)j0 * DD);
        int n4 = len * 32;
        for (int i = t; i < n4; i += 256) {
            float4 v = src[i];
            int j = i >> 5, cc = (i & 31) * 4;
            int off = j * 132 + (cc >> 5) * 33 + (cc & 31);
            ctx_s[off] = v.x; ctx_s[off + 1] = v.y;
            ctx_s[off + 2] = v.z; ctx_s[off + 3] = v.w;
        }
        __syncthreads();

        float acc = 0.f;
        int rowoff = jj * 132 + q * 33;
        #pragma unroll
        for (int cc = 0; cc < 32; ++cc)
            acc += ctx_s[rowoff + cc] * yr[cc];
        acc += __shfl_xor_sync(0xffffffffu, acc, 1);
        acc += __shfl_xor_sync(0xffffffffu, acc, 2);
        if (q == 0 && jj < len) {
            bool msk = (mb[j0 + jj] != 0);
            u_s[j0 + jj] = msk ? -CUDART_INF_F : tanhf(acc) * 5.f;
        }
    }
    __syncthreads();

    float Tval;
    {
        float tf = *(const float*)Tin;
        int   ti = *(const int*)Tin;
        Tval = (tf > 1e-6f && tf < 1e6f) ? tf : (float)ti;
    }
    float invT = 1.f / Tval;

    float mx = -CUDART_INF_F;
    for (int j = t; j < NN; j += 256) mx = fmaxf(mx, u_s[j]);
    #pragma unroll
    for (int o = 16; o > 0; o >>= 1)
        mx = fmaxf(mx, __shfl_xor_sync(0xffffffffu, mx, o));
    if (lane == 0) red_s[w] = mx;
    __syncthreads();
    if (w == 0) {
        float v = red_s[lane & 7];
        #pragma unroll
        for (int o = 4; o > 0; o >>= 1)
            v = fmaxf(v, __shfl_xor_sync(0xffffffffu, v, o));
        if (lane == 0) bm_s = v;
    }
    __syncthreads();
    mx = bm_s;

    float s = 0.f;
    for (int j = t; j < NN; j += 256) {
        float p = __expf((u_s[j] - mx) * invT);
        u_s[j] = p;
        s += p;
    }
    #pragma unroll
    for (int o = 16; o > 0; o >>= 1)
        s += __shfl_xor_sync(0xffffffffu, s, o);
    if (lane == 0) red_s[w] = s;
    __syncthreads();
    if (w == 0) {
        float v = red_s[lane & 7];
        #pragma unroll
        for (int o = 4; o > 0; o >>= 1)
            v += __shfl_xor_sync(0xffffffffu, v, o);
        if (lane == 0) bs_s = v;
    }
    __syncthreads();
    float inv = 1.f / bs_s;
    for (int j = t; j < NN; j += 256)
        out[(size_t)b * NN + j] = u_s[j] * inv;
}

// ---------------------------------------------------------------------------
extern "C" void kernel_launch(void* const* d_in, const int* in_sizes, int n_in,
                              void* d_out, int out_size) {
    const float* state  = (const float*)d_in[0];
    const float* ctx    = (const float*)d_in[1];
    const int*   mask   = (const int*)d_in[2];
    const float* Wq     = (const float*)d_in[3];
    const float* Wk_mha = (const float*)d_in[4];
    const float* Wv     = (const float*)d_in[5];
    const float* Wfc    = (const float*)d_in[6];
    const float* Wk     = (const float*)d_in[7];
    const void*  Tin    = d_in[8];
    float* out = (float*)d_out;

    k0_qa<<<BB / 4, 256>>>(state, Wq, Wk_mha);
    k1_mha<<<BB, 256>>>(ctx, mask);
    k2_y<<<BB / 8, 256>>>(Wv, Wfc, Wk);
    k3_ptr<<<BB, 256>>>(ctx, mask, Tin, out);
}